// round 16
// baseline (speedup 1.0000x reference)
#include <cuda_runtime.h>
#include <cuda_bf16.h>
#include <math.h>

// Problem constants
#define BB 2
#define SS 2048
#define DD 256
#define HH 8
#define FF 1024
#define DK 32
#define LL 3
#define BS (BB*SS)            // 4096 rows
#define BHS (BB*HH*SS)        // 32768 query slots
#define NEG_MAX (-3.402823466e38f)
#define SCALE 0.17677669529663687f   // 1/sqrt(32)
#define NCHUNK 4
#define CHUNK (SS/NCHUNK)     // 512 keys per split-KV chunk

typedef unsigned int uint32;

// ---------------- device scratch (static: no allocations allowed) ----------------
__device__ float g_x  [BS*DD];           // residual stream fp32
__device__ float g_t  [BS*DD];           // pre-LN temp fp32
__device__ __nv_bfloat16 g_xh[BS*DD], g_xl[BS*DD];      // x hi/lo
__device__ __nv_bfloat16 g_oh[BS*DD], g_ol[BS*DD];      // attn out hi/lo
__device__ __nv_bfloat16 g_hidh[BS*FF], g_hidl[BS*FF];  // FFN hidden hi/lo
__device__ unsigned int g_mpk[BB*SS*SS/32];             // packed mask bits
__device__ __nv_bfloat16 g_qh[BS*DD];    // Q bf16 [bh][s][dk]
__device__ __nv_bfloat16 g_kh[BS*DD];    // K bf16 [bh][s][dk]
__device__ __nv_bfloat16 g_vh[BS*DD];    // V bf16 transposed [bh][dk][s]
// split-KV partials
__device__ float g_pm[NCHUNK*BHS], g_pl[NCHUNK*BHS];
__device__ float g_pacc[(size_t)NCHUNK*BHS*DK];
// split/transposed weights: layout [n][k], hi/lo
__device__ __nv_bfloat16 Wqkv_h[LL*768*DD], Wqkv_l[LL*768*DD];
__device__ __nv_bfloat16 Wo_h [LL*DD*DD],  Wo_l [LL*DD*DD];
__device__ __nv_bfloat16 W1_h [LL*FF*DD],  W1_l [LL*FF*DD];
__device__ __nv_bfloat16 W2_h [LL*DD*FF],  W2_l [LL*DD*FF];

// ---------------- helpers ----------------
__device__ __forceinline__ void mma_bf16(float* c, const uint32* a, const uint32* b) {
    asm volatile(
        "mma.sync.aligned.m16n8k16.row.col.f32.bf16.bf16.f32 "
        "{%0,%1,%2,%3}, {%4,%5,%6,%7}, {%8,%9}, {%0,%1,%2,%3};\n"
        : "+f"(c[0]), "+f"(c[1]), "+f"(c[2]), "+f"(c[3])
        : "r"(a[0]), "r"(a[1]), "r"(a[2]), "r"(a[3]), "r"(b[0]), "r"(b[1]));
}
__device__ __forceinline__ void ldsm4(uint32* r, uint32 addr) {
    asm volatile("ldmatrix.sync.aligned.m8n8.x4.shared.b16 {%0,%1,%2,%3}, [%4];"
        : "=r"(r[0]), "=r"(r[1]), "=r"(r[2]), "=r"(r[3]) : "r"(addr));
}
__device__ __forceinline__ uint32 pack_bf16(float lo, float hi) {
    uint32 d;
    asm("cvt.rn.bf16x2.f32 %0, %1, %2;" : "=r"(d) : "f"(hi), "f"(lo));
    return d;
}
__device__ __forceinline__ void split2(float v0, float v1, uint32& hw, uint32& lw) {
    float h0 = __bfloat162float(__float2bfloat16(v0));
    float h1 = __bfloat162float(__float2bfloat16(v1));
    hw = pack_bf16(v0, v1);
    lw = pack_bf16(v0 - h0, v1 - h1);
}
__device__ __forceinline__ void cp16(uint32 saddr, const void* gptr) {
    asm volatile("cp.async.cg.shared.global [%0], [%1], 16;\n" :: "r"(saddr), "l"(gptr));
}
__device__ __forceinline__ void cp4(uint32 saddr, const void* gptr) {
    asm volatile("cp.async.ca.shared.global [%0], [%1], 4;\n" :: "r"(saddr), "l"(gptr));
}
#define CP_COMMIT()  asm volatile("cp.async.commit_group;\n" ::: "memory")
#define CP_WAIT(n)   asm volatile("cp.async.wait_group %0;\n" :: "n"(n) : "memory")

// ---------------- mask / pe / weight prep ----------------
__global__ void maskpack_kernel(const int* __restrict__ mask) {
    int w = blockIdx.x * 256 + threadIdx.x;
    const int4* p = (const int4*)(mask) + w * 8;
    unsigned int bits = 0;
#pragma unroll
    for (int j = 0; j < 8; j++) {
        int4 v = p[j];
        bits |= (v.x != 0 ? 1u : 0u) << (j * 4 + 0);
        bits |= (v.y != 0 ? 1u : 0u) << (j * 4 + 1);
        bits |= (v.z != 0 ? 1u : 0u) << (j * 4 + 2);
        bits |= (v.w != 0 ? 1u : 0u) << (j * 4 + 3);
    }
    g_mpk[w] = bits;
}

__global__ void addpe_kernel(const float* __restrict__ x, const float* __restrict__ pe) {
    int i = blockIdx.x * 256 + threadIdx.x;
    float v = x[i] + pe[i & (SS*DD - 1)];
    g_x[i] = v;
    __nv_bfloat16 h = __float2bfloat16(v);
    g_xh[i] = h;
    g_xl[i] = __float2bfloat16(v - __bfloat162float(h));
}

// coalesced weight transpose+split via 32x32 smem tile: Wt[l][n][k] from W[l][k][n]
__global__ void __launch_bounds__(256) wtsplit_kernel(const float* __restrict__ W,
                               __nv_bfloat16* __restrict__ Th,
                               __nv_bfloat16* __restrict__ Tl, int K, int N) {
    __shared__ float tile[32][33];
    int l = blockIdx.z;
    int k0 = blockIdx.x * 32, n0 = blockIdx.y * 32;
    int tx = threadIdx.x & 31, ty = threadIdx.x >> 5;   // 8 rows per pass
    const float* src = W + (size_t)l * K * N;
#pragma unroll
    for (int r = 0; r < 32; r += 8)
        tile[ty + r][tx] = src[(size_t)(k0 + ty + r) * N + n0 + tx];
    __syncthreads();
    __nv_bfloat16* dh = Th + (size_t)l * K * N;
    __nv_bfloat16* dl = Tl + (size_t)l * K * N;
#pragma unroll
    for (int r = 0; r < 32; r += 8) {
        float v = tile[tx][ty + r];
        __nv_bfloat16 h = __float2bfloat16(v);
        size_t di = (size_t)(n0 + ty + r) * K + k0 + tx;
        dh[di] = h;
        dl[di] = __float2bfloat16(v - __bfloat162float(h));
    }
}

// qkv weights, coalesced: W[l][h][d][kk] -> Wqkv[l][type*256+h*32+kk][d]
__global__ void __launch_bounds__(256) wqkvsplit_kernel(const float* __restrict__ Wq,
                                 const float* __restrict__ Wk,
                                 const float* __restrict__ Wv) {
    __shared__ float tile[32][33];
    int l = blockIdx.z;
    int type = blockIdx.y >> 3, h = blockIdx.y & 7;
    int d0 = blockIdx.x * 32;
    int tx = threadIdx.x & 31, ty = threadIdx.x >> 5;
    const float* W = (type == 0) ? Wq : ((type == 1) ? Wk : Wv);
    const float* src = W + (size_t)l * HH * DD * DK + (size_t)h * DD * DK;
#pragma unroll
    for (int r = 0; r < 32; r += 8)
        tile[ty + r][tx] = src[(size_t)(d0 + ty + r) * DK + tx];   // tx = kk (coalesced)
    __syncthreads();
    int nbase = type * 256 + h * 32;
#pragma unroll
    for (int r = 0; r < 32; r += 8) {
        int kk = ty + r, d = d0 + tx;
        float v = tile[tx][kk];
        __nv_bfloat16 hh = __float2bfloat16(v);
        size_t di = ((size_t)l * 768 + nbase + kk) * DD + d;
        Wqkv_h[di] = hh;
        Wqkv_l[di] = __float2bfloat16(v - __bfloat162float(hh));
    }
}

// ---------------- tensor-core split-bf16 GEMM, cp.async 2-stage + ldmatrix ----------------
// C[M=4096, N] = A[M,KD] * B^T (B stored [n][k] hi/lo). Tile 128x64, 256 thr, 3-mma hi/lo.
// EPI 0: g_t = acc + bias; EPI 1: g_hid hi/lo = relu(acc+bias);
// EPI 2: QKV scatter (type = blockIdx.y>>2: 0=Q,1=K,2=V)
#define KSTR 20   // u32 per smem row (32 bf16 + 16B pad)
#define ASZ (128*KSTR)
#define BSZ (64*KSTR)
#define SBUF (2*ASZ + 2*BSZ)          // u32 per pipeline buffer (30 KB)
#define GEMM_SMEM (2*SBUF*4)          // 60 KB dynamic smem
template<int KD, int EPI>
__global__ void __launch_bounds__(256) gemm_kernel(
    const __nv_bfloat16* __restrict__ Ah, const __nv_bfloat16* __restrict__ Al,
    const __nv_bfloat16* __restrict__ Bh, const __nv_bfloat16* __restrict__ Bl,
    const float* __restrict__ bias)
{
    extern __shared__ uint32 smem[];
    int t = threadIdx.x, lane = t & 31, w = t >> 5;
    int m0 = blockIdx.x * 128;
    int g = lane >> 2, q4 = lane & 3;
    int mw = w * 16;

    float c[8][4];
#pragma unroll
    for (int nb = 0; nb < 8; nb++) { c[nb][0] = c[nb][1] = c[nb][2] = c[nb][3] = 0.f; }

    // staging coordinates
    int arow = t >> 1, ac4 = (t & 1) * 2;      // A: 2x16B per thread (per part)
    int brow = t >> 2, bc4 = t & 3;            // B: 1x16B per thread (per part)
    const uint4* gAh = (const uint4*)(Ah + (size_t)(m0 + arow) * KD);
    const uint4* gAl = (const uint4*)(Al + (size_t)(m0 + arow) * KD);
    const uint4* gBh = (const uint4*)(Bh + (size_t)((size_t)blockIdx.y * 64 + brow) * KD);
    const uint4* gBl = (const uint4*)(Bl + (size_t)((size_t)blockIdx.y * 64 + brow) * KD);
    uint32 base = (uint32)__cvta_generic_to_shared(smem);
    uint32 sA  = base + (arow * KSTR + ac4 * 4) * 4;
    uint32 sAl = sA + ASZ * 4;
    uint32 sB  = base + (2 * ASZ + brow * KSTR + bc4 * 4) * 4;
    uint32 sBl = sB + BSZ * 4;

    // ldmatrix lane addresses (bytes, buf 0)
    uint32 aAh0 = base + ((mw + (lane & 15)) * KSTR + ((lane & 16) ? 4 : 0)) * 4;
    uint32 aAl0 = aAh0 + ASZ * 4;
    // B x4: lanes 0-7 rows r..r+7 col 0; 8-15 col +4; 16-23 rows +8 col 0; 24-31 rows +8 col +4
    uint32 aBh0 = base + (2 * ASZ + ((lane & 7) + ((lane & 16) ? 8 : 0)) * KSTR
                          + ((lane & 8) ? 4 : 0)) * 4;
    uint32 aBl0 = aBh0 + BSZ * 4;

    const int NCH = KD / 32;

    // prologue: chunk 0 -> buf 0
    {
        cp16(sA,       gAh + ac4);     cp16(sA + 16,  gAh + ac4 + 1);
        cp16(sAl,      gAl + ac4);     cp16(sAl + 16, gAl + ac4 + 1);
        cp16(sB,       gBh + bc4);
        cp16(sBl,      gBl + bc4);
        CP_COMMIT();
    }

    for (int i = 0; i < NCH; i++) {
        int buf = i & 1;
        __syncthreads();                       // all done computing from buf^1
        if (i + 1 < NCH) {
            uint32 off = (uint32)((buf ^ 1) * SBUF * 4);
            int k8 = (i + 1) * 4;              // k0/8 in uint4 units
            cp16(sA + off,       gAh + k8 + ac4);
            cp16(sA + off + 16,  gAh + k8 + ac4 + 1);
            cp16(sAl + off,      gAl + k8 + ac4);
            cp16(sAl + off + 16, gAl + k8 + ac4 + 1);
            cp16(sB + off,       gBh + k8 + bc4);
            cp16(sBl + off,      gBl + k8 + bc4);
            CP_COMMIT();
            CP_WAIT(1);                        // chunk i landed; i+1 in flight
        } else {
            CP_WAIT(0);
        }
        __syncthreads();                       // chunk i visible

        uint32 bufoff = (uint32)(buf * SBUF * 4);
#pragma unroll
        for (int kh = 0; kh < 2; kh++) {
            uint32 ah[4], al[4];
            ldsm4(ah, aAh0 + bufoff + kh * 32);
            ldsm4(al, aAl0 + bufoff + kh * 32);
#pragma unroll
            for (int nb2 = 0; nb2 < 4; nb2++) {
                uint32 nboff = bufoff + (uint32)(nb2 * 16 * KSTR * 4) + kh * 32;
                uint32 b4[4], bl4[4];
                ldsm4(b4,  aBh0 + nboff);
                ldsm4(bl4, aBl0 + nboff);
                mma_bf16(c[2 * nb2],     ah, b4);
                mma_bf16(c[2 * nb2],     al, b4);
                mma_bf16(c[2 * nb2],     ah, bl4);
                mma_bf16(c[2 * nb2 + 1], ah, b4 + 2);
                mma_bf16(c[2 * nb2 + 1], al, b4 + 2);
                mma_bf16(c[2 * nb2 + 1], ah, bl4 + 2);
            }
        }
    }

    int r0 = m0 + mw + g;
    if (EPI == 0) {
#pragma unroll
        for (int nb = 0; nb < 8; nb++) {
            int col = blockIdx.y * 64 + nb * 8 + 2 * q4;
            float b0 = bias[col], b1 = bias[col + 1];
            *(float2*)&g_t[(size_t)r0 * DD + col] =
                make_float2(c[nb][0] + b0, c[nb][1] + b1);
            *(float2*)&g_t[(size_t)(r0 + 8) * DD + col] =
                make_float2(c[nb][2] + b0, c[nb][3] + b1);
        }
    } else if (EPI == 1) {
#pragma unroll
        for (int nb = 0; nb < 8; nb++) {
            int col = blockIdx.y * 64 + nb * 8 + 2 * q4;
            float b0 = bias[col], b1 = bias[col + 1];
            float v0 = fmaxf(c[nb][0] + b0, 0.f), v1 = fmaxf(c[nb][1] + b1, 0.f);
            float v2 = fmaxf(c[nb][2] + b0, 0.f), v3 = fmaxf(c[nb][3] + b1, 0.f);
            uint32 hw, lw;
            split2(v0, v1, hw, lw);
            ((uint32*)g_hidh)[((size_t)r0 * FF + col) >> 1] = hw;
            ((uint32*)g_hidl)[((size_t)r0 * FF + col) >> 1] = lw;
            split2(v2, v3, hw, lw);
            ((uint32*)g_hidh)[((size_t)(r0 + 8) * FF + col) >> 1] = hw;
            ((uint32*)g_hidl)[((size_t)(r0 + 8) * FF + col) >> 1] = lw;
        }
    } else {
        // QKV scatter: blockIdx.y 0..11, type 0=Q,1=K,2=V
        int type = blockIdx.y >> 2;
        int nbase = (blockIdx.y & 3) * 64;
        int b = r0 >> 11, s0 = r0 & 2047;
#pragma unroll
        for (int nb = 0; nb < 8; nb++) {
            int nl = nbase + nb * 8 + 2 * q4;
            int h = nl >> 5, kk = nl & 31;
            if (type == 2) {
                size_t vb = ((size_t)(b * HH + h) * DK + kk) * SS;
                g_vh[vb + s0]             = __float2bfloat16(c[nb][0]);
                g_vh[vb + SS + s0]        = __float2bfloat16(c[nb][1]);
                g_vh[vb + s0 + 8]         = __float2bfloat16(c[nb][2]);
                g_vh[vb + SS + s0 + 8]    = __float2bfloat16(c[nb][3]);
            } else {
                __nv_bfloat16* dst = (type == 0) ? g_qh : g_kh;
                size_t i0 = (((size_t)(b * HH + h) * SS + s0) * DK + kk) >> 1;
                ((uint32*)dst)[i0]       = pack_bf16(c[nb][0], c[nb][1]);
                ((uint32*)dst)[i0 + 128] = pack_bf16(c[nb][2], c[nb][3]);
            }
        }
    }
}

// ------------- tensor-core flash attention, split-KV x4, cp.async 2-stage, 128-key tiles -------------
#define KSTRIDE 20
#define VSTR2 68    // u32 per Vt row: 128 keys (64 u32) + 16B pad
__global__ void __launch_bounds__(128) attn_mma_kernel() {
    __shared__ uint32 Ks[2][128 * KSTRIDE];
    __shared__ uint32 Vt[2][32 * VSTR2];
    __shared__ uint32 Msk[2][256];        // 64 q-rows x 4 words

    int t = threadIdx.x;
    int lane = t & 31, w = t >> 5;
    int cid = blockIdx.x & (NCHUNK - 1);
    int qb = blockIdx.x >> 2;             // NCHUNK==4
    int bh = qb >> 5;
    int qt = qb & 31;
    int b = bh >> 3;
    int m0 = w * 16;
    int g = lane >> 2, q4 = lane & 3;

    int sq_lo = qt * 64 + m0 + g;
    const uint32* qrow_lo = (const uint32*)(g_qh + ((size_t)bh * SS + sq_lo) * DK);
    const uint32* qrow_hi = qrow_lo + 8 * (DK / 2);
    uint32 aq[2][4];
#pragma unroll
    for (int kk = 0; kk < 2; kk++) {
        int base = kk * 8 + q4;
        aq[kk][0] = qrow_lo[base];     aq[kk][1] = qrow_hi[base];
        aq[kk][2] = qrow_lo[base + 4]; aq[kk][3] = qrow_hi[base + 4];
    }

    float mr_lo = -INFINITY, mr_hi = -INFINITY, l_lo = 0.f, l_hi = 0.f;
    float o[4][4];
#pragma unroll
    for (int jn = 0; jn < 4; jn++)
#pragma unroll
        for (int e = 0; e < 4; e++) o[jn][e] = 0.f;

    const float4* ksrc = (const float4*)(g_kh + (size_t)bh * SS * DK);
    const unsigned int* mbase = g_mpk + (size_t)(b * SS + qt * 64) * (SS / 32);

    // staging coordinates: K tile 128 rows x 32 bf16 (512 float4), V 32 rows x 64 u32 (512 float4)
    int krow = t >> 2, kc4 = t & 3;       // K rows: krow + 32j
    int vrow_s = t >> 3, vc4 = t & 7;     // V rows vrow_s, vrow_s+16; cols vc4, vc4+8
    uint32 ksad[4], vsad[4];
#pragma unroll
    for (int j = 0; j < 4; j++)
        ksad[j] = (uint32)__cvta_generic_to_shared(&Ks[0][(krow + 32 * j) * KSTRIDE + kc4 * 4]);
    vsad[0] = (uint32)__cvta_generic_to_shared(&Vt[0][vrow_s * VSTR2 + vc4 * 4]);
    vsad[1] = (uint32)__cvta_generic_to_shared(&Vt[0][vrow_s * VSTR2 + (vc4 + 8) * 4]);
    vsad[2] = (uint32)__cvta_generic_to_shared(&Vt[0][(vrow_s + 16) * VSTR2 + vc4 * 4]);
    vsad[3] = (uint32)__cvta_generic_to_shared(&Vt[0][(vrow_s + 16) * VSTR2 + (vc4 + 8) * 4]);
    uint32 ms0 = (uint32)__cvta_generic_to_shared(&Msk[0][2 * t]);
    const uint32 kbufsz = (uint32)(128 * KSTRIDE * 4);
    const uint32 vbufsz = (uint32)(32 * VSTR2 * 4);

    int kstart = cid * CHUNK;
    const int NT = CHUNK / 128;

    // prologue: tile 0 -> buf 0
    {
        int k0 = kstart;
#pragma unroll
        for (int j = 0; j < 4; j++)
            cp16(ksad[j], ksrc + k0 * 4 + t + j * 128);
        cp16(vsad[0], (const float4*)(g_vh + ((size_t)bh * DK + vrow_s) * SS + k0) + vc4);
        cp16(vsad[1], (const float4*)(g_vh + ((size_t)bh * DK + vrow_s) * SS + k0) + vc4 + 8);
        cp16(vsad[2], (const float4*)(g_vh + ((size_t)bh * DK + vrow_s + 16) * SS + k0) + vc4);
        cp16(vsad[3], (const float4*)(g_vh + ((size_t)bh * DK + vrow_s + 16) * SS + k0) + vc4 + 8);
        cp4(ms0,     mbase + (size_t)((2 * t) >> 2) * (SS / 32) + (k0 >> 5) + ((2 * t) & 3));
        cp4(ms0 + 4, mbase + (size_t)((2 * t + 1) >> 2) * (SS / 32) + (k0 >> 5) + ((2 * t + 1) & 3));
        CP_COMMIT();
    }

    for (int i = 0; i < NT; i++) {
        int buf = i & 1;
        __syncthreads();
        if (i + 1 < NT) {
            int k0 = kstart + (i + 1) * 128;
            uint32 kb = (buf ^ 1) ? kbufsz : 0u;
            uint32 vb = (buf ^ 1) ? vbufsz : 0u;
            uint32 mb = (buf ^ 1) ? 1024u : 0u;
#pragma unroll
            for (int j = 0; j < 4; j++)
                cp16(ksad[j] + kb, ksrc + k0 * 4 + t + j * 128);
            cp16(vsad[0] + vb, (const float4*)(g_vh + ((size_t)bh * DK + vrow_s) * SS + k0) + vc4);
            cp16(vsad[1] + vb, (const float4*)(g_vh + ((size_t)bh * DK + vrow_s) * SS + k0) + vc4 + 8);
            cp16(vsad[2] + vb, (const float4*)(g_vh + ((size_t)bh * DK + vrow_s + 16) * SS + k0) + vc4);
            cp16(vsad[3] + vb, (const float4*)(g_vh + ((size_t)bh * DK + vrow_s + 16) * SS + k0) + vc4 + 8);
            cp4(ms0 + mb,     mbase + (size_t)((2 * t) >> 2) * (SS / 32) + (k0 >> 5) + ((2 * t) & 3));
            cp4(ms0 + mb + 4, mbase + (size_t)((2 * t + 1) >> 2) * (SS / 32) + (k0 >> 5) + ((2 * t + 1) & 3));
            CP_COMMIT();
            CP_WAIT(1);
        } else {
            CP_WAIT(0);
        }
        __syncthreads();

        // ---- compute 128-key tile from buf ----
        float c[16][4];
#pragma unroll
        for (int j = 0; j < 16; j++) { c[j][0] = c[j][1] = c[j][2] = c[j][3] = 0.f; }
#pragma unroll
        for (int j = 0; j < 16; j++) {
            int kr = (8 * j + g) * KSTRIDE;
            uint32 bfr[2];
            bfr[0] = Ks[buf][kr + q4];     bfr[1] = Ks[buf][kr + q4 + 4];
            mma_bf16(c[j], aq[0], bfr);
            bfr[0] = Ks[buf][kr + 8 + q4]; bfr[1] = Ks[buf][kr + 8 + q4 + 4];
            mma_bf16(c[j], aq[1], bfr);
        }
        uint32 ml[4], mh[4];
#pragma unroll
        for (int wd = 0; wd < 4; wd++) {
            ml[wd] = Msk[buf][(m0 + g) * 4 + wd];
            mh[wd] = Msk[buf][(m0 + g + 8) * 4 + wd];
        }
#pragma unroll
        for (int j = 0; j < 16; j++) {
            uint32 wl = ml[j >> 2], wh = mh[j >> 2];
#pragma unroll
            for (int e = 0; e < 2; e++) {
                int bp = ((8 * j) & 31) + 2 * q4 + e;
                c[j][e]     = ((wl >> bp) & 1u) ? NEG_MAX : c[j][e] * SCALE;
                c[j][2 + e] = ((wh >> bp) & 1u) ? NEG_MAX : c[j][2 + e] * SCALE;
            }
        }
        float mx_lo = c[0][0], mx_hi = c[0][2];
#pragma unroll
        for (int j = 0; j < 16; j++) {
            mx_lo = fmaxf(mx_lo, fmaxf(c[j][0], c[j][1]));
            mx_hi = fmaxf(mx_hi, fmaxf(c[j][2], c[j][3]));
        }
        mx_lo = fmaxf(mx_lo, __shfl_xor_sync(0xffffffffu, mx_lo, 1));
        mx_lo = fmaxf(mx_lo, __shfl_xor_sync(0xffffffffu, mx_lo, 2));
        mx_hi = fmaxf(mx_hi, __shfl_xor_sync(0xffffffffu, mx_hi, 1));
        mx_hi = fmaxf(mx_hi, __shfl_xor_sync(0xffffffffu, mx_hi, 2));
        float mn_lo = fmaxf(mr_lo, mx_lo), mn_hi = fmaxf(mr_hi, mx_hi);
        float corr_lo = __expf(mr_lo - mn_lo), corr_hi = __expf(mr_hi - mn_hi);
        mr_lo = mn_lo; mr_hi = mn_hi;

        float sum_lo = 0.f, sum_hi = 0.f;
#pragma unroll
        for (int j = 0; j < 16; j++) {
            c[j][0] = __expf(c[j][0] - mn_lo); sum_lo += c[j][0];
            c[j][1] = __expf(c[j][1] - mn_lo); sum_lo += c[j][1];
            c[j][2] = __expf(c[j][2] - mn_hi); sum_hi += c[j][2];
            c[j][3] = __expf(c[j][3] - mn_hi); sum_hi += c[j][3];
        }
        sum_lo += __shfl_xor_sync(0xffffffffu, sum_lo, 1);
        sum_lo += __shfl_xor_sync(0xffffffffu, sum_lo, 2);
        sum_hi += __shfl_xor_sync(0xffffffffu, sum_hi, 1);
        sum_hi += __shfl_xor_sync(0xffffffffu, sum_hi, 2);
        l_lo = l_lo * corr_lo + sum_lo;
        l_hi = l_hi * corr_hi + sum_hi;
#pragma unroll
        for (int jn = 0; jn < 4; jn++) {
            o[jn][0] *= corr_lo; o[jn][1] *= corr_lo;
            o[jn][2] *= corr_hi; o[jn][3] *= corr_hi;
        }
        uint32 pf[8][4];
#pragma unroll
        for (int jj = 0; jj < 8; jj++) {
            pf[jj][0] = pack_bf16(c[2 * jj][0],     c[2 * jj][1]);
            pf[jj][1] = pack_bf16(c[2 * jj][2],     c[2 * jj][3]);
            pf[jj][2] = pack_bf16(c[2 * jj + 1][0], c[2 * jj + 1][1]);
            pf[jj][3] = pack_bf16(c[2 * jj + 1][2], c[2 * jj + 1][3]);
        }
#pragma unroll
        for (int jn = 0; jn < 4; jn++) {
            int vr = (8 * jn + g) * VSTR2;
#pragma unroll
            for (int jj = 0; jj < 8; jj++) {
                uint32 bfr[2];
                bfr[0] = Vt[buf][vr + 8 * jj + q4];
                bfr[1] = Vt[buf][vr + 8 * jj + q4 + 4];
                mma_bf16(o[jn], pf[jj], bfr);
            }
        }
    }
    // store unnormalized partials
    int qidx = bh * SS + sq_lo;       // rows qidx, qidx+8
    float* pp = g_pacc + ((size_t)cid * BHS + qidx) * DK;
#pragma unroll
    for (int jn = 0; jn < 4; jn++) {
        int col = 8 * jn + 2 * q4;
        *(float2*)&pp[col]          = make_float2(o[jn][0], o[jn][1]);
        *(float2*)&pp[8 * DK + col] = make_float2(o[jn][2], o[jn][3]);
    }
    if (q4 == 0) {
        g_pm[cid * BHS + qidx] = mr_lo;     g_pl[cid * BHS + qidx] = l_lo;
        g_pm[cid * BHS + qidx + 8] = mr_hi; g_pl[cid * BHS + qidx + 8] = l_hi;
    }
}

// merge NCHUNK partials, normalize, write hi/lo attn output (head-concat layout)
__global__ void __launch_bounds__(256) attn_combine_kernel() {
    int q = blockIdx.x * 256 + threadIdx.x;   // 0..BHS-1
    float gm = -INFINITY;
#pragma unroll
    for (int c = 0; c < NCHUNK; c++) gm = fmaxf(gm, g_pm[c * BHS + q]);
    float wgt[NCHUNK];
    float L = 0.f;
#pragma unroll
    for (int c = 0; c < NCHUNK; c++) {
        wgt[c] = __expf(g_pm[c * BHS + q] - gm);
        L += g_pl[c * BHS + q] * wgt[c];
    }
    float inv = 1.f / L;
#pragma unroll
    for (int c = 0; c < NCHUNK; c++) wgt[c] *= inv;

    int bh = q >> 11, sq = q & 2047;
    int b = bh >> 3, h = bh & 7;
    size_t obase = ((size_t)b * SS + sq) * DD + h * DK;
    uint32* doh = (uint32*)g_oh + (obase >> 1);
    uint32* dol = (uint32*)g_ol + (obase >> 1);
#pragma unroll
    for (int i = 0; i < 8; i++) {
        float r0 = 0.f, r1 = 0.f, r2 = 0.f, r3 = 0.f;
#pragma unroll
        for (int c = 0; c < NCHUNK; c++) {
            float4 a = ((const float4*)(g_pacc + ((size_t)c * BHS + q) * DK))[i];
            r0 = fmaf(a.x, wgt[c], r0); r1 = fmaf(a.y, wgt[c], r1);
            r2 = fmaf(a.z, wgt[c], r2); r3 = fmaf(a.w, wgt[c], r3);
        }
        uint32 hw, lw;
        split2(r0, r1, hw, lw);
        doh[i * 2] = hw; dol[i * 2] = lw;
        split2(r2, r3, hw, lw);
        doh[i * 2 + 1] = hw; dol[i * 2 + 1] = lw;
    }
}

// residual + layernorm: warp per row, 8 rows/block, shfl-only reductions.
// outp == nullptr: write g_x + hi/lo. outp != nullptr (last layer): write outp only.
__global__ void __launch_bounds__(256) ln_kernel(const float* __restrict__ gam,
                                                 const float* __restrict__ bet,
                                                 float* __restrict__ outp) {
    int lane = threadIdx.x & 31, wrp = threadIdx.x >> 5;
    int row = blockIdx.x * 8 + wrp;
    const float4* t4 = (const float4*)(g_t + (size_t)row * DD) + lane * 2;
    const float4* x4 = (const float4*)(g_x + (size_t)row * DD) + lane * 2;
    float4 a0 = t4[0], a1 = t4[1], b0 = x4[0], b1 = x4[1];
    float v[8] = { a0.x + b0.x, a0.y + b0.y, a0.z + b0.z, a0.w + b0.w,
                   a1.x + b1.x, a1.y + b1.y, a1.z + b1.z, a1.w + b1.w };
    float s = 0.f;
#pragma unroll
    for (int i = 0; i < 8; i++) s += v[i];
#pragma unroll
    for (int o = 16; o; o >>= 1) s += __shfl_xor_sync(0xffffffffu, s, o);
    float mu = s * (1.f / DD);
    float s2 = 0.f;
#pragma unroll
    for (int i = 0; i < 8; i++) { float d = v[i] - mu; s2 += d * d; }
#pragma unroll
    for (int o = 16; o; o >>= 1) s2 += __shfl_xor_sync(0xffffffffu, s2, o);
    float rstd = rsqrtf(s2 * (1.f / DD) + 1e-7f);

    const float4* g4 = (const float4*)gam + lane * 2;
    const float4* be4 = (const float4*)bet + lane * 2;
    float4 gg0 = g4[0], gg1 = g4[1], bb0 = be4[0], bb1 = be4[1];
    float out[8];
    out[0] = (v[0] - mu) * rstd * gg0.x + bb0.x;
    out[1] = (v[1] - mu) * rstd * gg0.y + bb0.y;
    out[2] = (v[2] - mu) * rstd * gg0.z + bb0.z;
    out[3] = (v[3] - mu) * rstd * gg0.w + bb0.w;
    out[4] = (v[4] - mu) * rstd * gg1.x + bb1.x;
    out[5] = (v[5] - mu) * rstd * gg1.y + bb1.y;
    out[6] = (v[6] - mu) * rstd * gg1.z + bb1.z;
    out[7] = (v[7] - mu) * rstd * gg1.w + bb1.w;

    if (outp) {
        float4* oo = (float4*)(outp + (size_t)row * DD) + lane * 2;
        oo[0] = make_float4(out[0], out[1], out[2], out[3]);
        oo[1] = make_float4(out[4], out[5], out[6], out[7]);
    } else {
        float4* xo = (float4*)(g_x + (size_t)row * DD) + lane * 2;
        xo[0] = make_float4(out[0], out[1], out[2], out[3]);
        xo[1] = make_float4(out[4], out[5], out[6], out[7]);
        uint32 hw[4], lw[4];
#pragma unroll
        for (int i = 0; i < 4; i++) split2(out[2 * i], out[2 * i + 1], hw[i], lw[i]);
        size_t wi = ((size_t)row * DD) / 2 + lane * 4;
        *(uint4*)((uint32*)g_xh + wi) = *(uint4*)hw;
        *(uint4*)((uint32*)g_xl + wi) = *(uint4*)lw;
    }
}

// ---------------- launch ----------------
extern "C" void kernel_launch(void* const* d_in, const int* in_sizes, int n_in,
                              void* d_out, int out_size) {
    const float* x  = (const float*)d_in[0];
    const int*   mask = (const int*)d_in[1];     // jnp bool promoted to int32
    const float* pe = (const float*)d_in[2];
    const float* Wq = (const float*)d_in[3];
    const float* Wk = (const float*)d_in[4];
    const float* Wv = (const float*)d_in[5];
    const float* Wo = (const float*)d_in[6];
    const float* bo = (const float*)d_in[7];
    const float* ln1_g = (const float*)d_in[8];
    const float* ln1_b = (const float*)d_in[9];
    const float* W1 = (const float*)d_in[10];
    const float* b1 = (const float*)d_in[11];
    const float* W2 = (const float*)d_in[12];
    const float* b2 = (const float*)d_in[13];
    const float* ln2_g = (const float*)d_in[14];
    const float* ln2_b = (const float*)d_in[15];

    void *p_xh, *p_xl, *p_oh, *p_ol, *p_hh, *p_hl;
    void *p_wqkvh, *p_wqkvl, *p_woh, *p_wol, *p_w1h, *p_w1l, *p_w2h, *p_w2l;
    cudaGetSymbolAddress(&p_xh, g_xh);   cudaGetSymbolAddress(&p_xl, g_xl);
    cudaGetSymbolAddress(&p_oh, g_oh);   cudaGetSymbolAddress(&p_ol, g_ol);
    cudaGetSymbolAddress(&p_hh, g_hidh); cudaGetSymbolAddress(&p_hl, g_hidl);
    cudaGetSymbolAddress(&p_wqkvh, Wqkv_h); cudaGetSymbolAddress(&p_wqkvl, Wqkv_l);
    cudaGetSymbolAddress(&p_woh, Wo_h);  cudaGetSymbolAddress(&p_wol, Wo_l);
    cudaGetSymbolAddress(&p_w1h, W1_h);  cudaGetSymbolAddress(&p_w1l, W1_l);
    cudaGetSymbolAddress(&p_w2h, W2_h);  cudaGetSymbolAddress(&p_w2l, W2_l);
    const __nv_bfloat16 *xh = (const __nv_bfloat16*)p_xh, *xl = (const __nv_bfloat16*)p_xl;
    const __nv_bfloat16 *oh = (const __nv_bfloat16*)p_oh, *ol = (const __nv_bfloat16*)p_ol;
    const __nv_bfloat16 *hh = (const __nv_bfloat16*)p_hh, *hl = (const __nv_bfloat16*)p_hl;

    // dynamic-smem opt-in for all gemm instantiations (host-side, capture-safe)
    cudaFuncSetAttribute(gemm_kernel<256, 0>,  cudaFuncAttributeMaxDynamicSharedMemorySize, GEMM_SMEM);
    cudaFuncSetAttribute(gemm_kernel<256, 1>,  cudaFuncAttributeMaxDynamicSharedMemorySize, GEMM_SMEM);
    cudaFuncSetAttribute(gemm_kernel<256, 2>,  cudaFuncAttributeMaxDynamicSharedMemorySize, GEMM_SMEM);
    cudaFuncSetAttribute(gemm_kernel<1024, 0>, cudaFuncAttributeMaxDynamicSharedMemorySize, GEMM_SMEM);

    // weight prep (idempotent, coalesced tile transposes)
    wqkvsplit_kernel<<<dim3(DD / 32, 24, LL), 256>>>(Wq, Wk, Wv);
    wtsplit_kernel<<<dim3(DD / 32, DD / 32, LL), 256>>>(Wo, (__nv_bfloat16*)p_woh, (__nv_bfloat16*)p_wol, DD, DD);
    wtsplit_kernel<<<dim3(DD / 32, FF / 32, LL), 256>>>(W1, (__nv_bfloat16*)p_w1h, (__nv_bfloat16*)p_w1l, DD, FF);
    wtsplit_kernel<<<dim3(FF / 32, DD / 32, LL), 256>>>(W2, (__nv_bfloat16*)p_w2h, (__nv_bfloat16*)p_w2l, FF, DD);
    maskpack_kernel<<<(BB*SS*SS/32) / 256, 256>>>(mask);
    addpe_kernel<<<BS * DD / 256, 256>>>(x, pe);

    for (int l = 0; l < LL; l++) {
        const __nv_bfloat16* wqh = (const __nv_bfloat16*)p_wqkvh + (size_t)l * 768 * DD;
        const __nv_bfloat16* wql = (const __nv_bfloat16*)p_wqkvl + (size_t)l * 768 * DD;
        const __nv_bfloat16* woh2 = (const __nv_bfloat16*)p_woh + (size_t)l * DD * DD;
        const __nv_bfloat16* wol2 = (const __nv_bfloat16*)p_wol + (size_t)l * DD * DD;
        const __nv_bfloat16* w1h2 = (const __nv_bfloat16*)p_w1h + (size_t)l * FF * DD;
        const __nv_bfloat16* w1l2 = (const __nv_bfloat16*)p_w1l + (size_t)l * FF * DD;
        const __nv_bfloat16* w2h2 = (const __nv_bfloat16*)p_w2h + (size_t)l * DD * FF;
        const __nv_bfloat16* w2l2 = (const __nv_bfloat16*)p_w2l + (size_t)l * DD * FF;

        gemm_kernel<256, 2><<<dim3(32, 12), 256, GEMM_SMEM>>>(xh, xl, wqh, wql, nullptr);       // QKV
        attn_mma_kernel<<<BB * HH * (SS / 64) * NCHUNK, 128>>>();
        attn_combine_kernel<<<BHS / 256, 256>>>();
        gemm_kernel<256, 0><<<dim3(32, 4), 256, GEMM_SMEM>>>(oh, ol, woh2, wol2, bo + l * DD);  // Wo
        ln_kernel<<<BS / 8, 256>>>(ln1_g + l * DD, ln1_b + l * DD, nullptr);
        gemm_kernel<256, 1><<<dim3(32, 16), 256, GEMM_SMEM>>>(xh, xl, w1h2, w1l2, b1 + l * FF); // FFN1
        gemm_kernel<1024, 0><<<dim3(32, 4), 256, GEMM_SMEM>>>(hh, hl, w2h2, w2l2, b2 + l * DD); // FFN2
        ln_kernel<<<BS / 8, 256>>>(ln2_g + l * DD, ln2_b + l * DD,
                                   (l == LL - 1) ? (float*)d_out : nullptr);
    }
}